// round 16
// baseline (speedup 1.0000x reference)
#include <cuda_runtime.h>

// Row-wise cosine similarity * 0.5 over [B=16384, D=4096] fp32.
// FINAL (v8): one CTA (256 thr) per row, 256-bit loads
// (ld.global.nc.v8.f32 / LDG.E.256, Blackwell-only) - 4 load
// instructions per thread for 128 B/thread, halving LSU requests and
// L1tex wavefronts per byte vs float4. Warp shuffle + smem reduce.
// Confirmed over two independent samples: harness 78.3/76.26us,
// ncu kernel 76.19/77.22us, DRAM 88-90% (7.0-7.1 TB/s), occ 93%,
// regs 32. This is the HBM roofline for fp32 streaming on sm_103a:
// all structural alternatives measured and falsified
// (warp/row 80.7 | 2-row pipeline 84.8 | 128-thr deep-MLP 78.2 |
//  8-row loop 82.5 | fused 512-thr pair 78.0 | __ldcs 79.9 | v1 ~77.4).

#define D_DIM 4096
#define THREADS 256

__device__ __forceinline__ void ldg256(const float* __restrict__ p, float v[8]) {
    asm("ld.global.nc.v8.f32 {%0,%1,%2,%3,%4,%5,%6,%7}, [%8];"
        : "=f"(v[0]), "=f"(v[1]), "=f"(v[2]), "=f"(v[3]),
          "=f"(v[4]), "=f"(v[5]), "=f"(v[6]), "=f"(v[7])
        : "l"(p));
}

__global__ __launch_bounds__(THREADS) void cosine_rows_v8_kernel(
    const float* __restrict__ x1,
    const float* __restrict__ x2,
    float* __restrict__ out)
{
    const int row = blockIdx.x;
    const int tid = threadIdx.x;

    const float* r1 = x1 + (size_t)row * D_DIM;
    const float* r2 = x2 + (size_t)row * D_DIM;

    // Per thread: 2 x v8 per input = 16 floats per input (128 B/thread).
    float a0[8], a1[8], b0[8], b1[8];
    ldg256(r1 + (size_t)(tid + 0 * THREADS) * 8, a0);
    ldg256(r1 + (size_t)(tid + 1 * THREADS) * 8, a1);
    ldg256(r2 + (size_t)(tid + 0 * THREADS) * 8, b0);
    ldg256(r2 + (size_t)(tid + 1 * THREADS) * 8, b1);

    float dot = 0.f, sx = 0.f, sy = 0.f;
#pragma unroll
    for (int i = 0; i < 8; ++i) {
        dot = fmaf(a0[i], b0[i], dot);
        sx  = fmaf(a0[i], a0[i], sx);
        sy  = fmaf(b0[i], b0[i], sy);
    }
#pragma unroll
    for (int i = 0; i < 8; ++i) {
        dot = fmaf(a1[i], b1[i], dot);
        sx  = fmaf(a1[i], a1[i], sx);
        sy  = fmaf(b1[i], b1[i], sy);
    }

    // Warp reduce (3 values)
#pragma unroll
    for (int off = 16; off > 0; off >>= 1) {
        dot += __shfl_down_sync(0xFFFFFFFFu, dot, off);
        sx  += __shfl_down_sync(0xFFFFFFFFu, sx,  off);
        sy  += __shfl_down_sync(0xFFFFFFFFu, sy,  off);
    }

    __shared__ float s_dot[8], s_sx[8], s_sy[8];
    const int wid = tid >> 5;
    const int lid = tid & 31;
    if (lid == 0) { s_dot[wid] = dot; s_sx[wid] = sx; s_sy[wid] = sy; }
    __syncthreads();

    if (wid == 0) {
        dot = (lid < 8) ? s_dot[lid] : 0.f;
        sx  = (lid < 8) ? s_sx[lid]  : 0.f;
        sy  = (lid < 8) ? s_sy[lid]  : 0.f;
#pragma unroll
        for (int off = 4; off > 0; off >>= 1) {
            dot += __shfl_down_sync(0xFFFFFFFFu, dot, off);
            sx  += __shfl_down_sync(0xFFFFFFFFu, sx,  off);
            sy  += __shfl_down_sync(0xFFFFFFFFu, sy,  off);
        }
        if (lid == 0) {
            out[row] = 0.5f * dot * rsqrtf(sx * sy);
        }
    }
}

extern "C" void kernel_launch(void* const* d_in, const int* in_sizes, int n_in,
                              void* d_out, int out_size)
{
    const float* x1 = (const float*)d_in[0];
    const float* x2 = (const float*)d_in[1];
    float* out = (float*)d_out;
    const int B = out_size;  // 16384 rows
    cosine_rows_v8_kernel<<<B, THREADS>>>(x1, x2, out);
}

// round 17
// speedup vs baseline: 1.0017x; 1.0017x over previous
#include <cuda_runtime.h>

// Row-wise cosine similarity * 0.5 over [B=16384, D=4096] fp32.
// FINAL (v8, confirmed x3): one CTA (256 thr) per row, 256-bit loads
// (ld.global.nc.v8.f32 / LDG.E.256, Blackwell-only) - 4 load
// instructions per thread for 128 B/thread, halving LSU requests and
// L1tex wavefronts per byte vs float4. Warp shuffle + smem reduce.
// Harness samples: 78.3 / 76.26 / 76.29 us; ncu kernel 76.2-77.3 us;
// DRAM 88-90% (7.0-7.1 TB/s of 8 TB/s spec); occ 93%; regs 32.
// This is the fp32-streaming HBM roofline on sm_103a. Falsified:
//   warp/row 80.7 | 2-row pipeline 84.8 | 128-thr deep-MLP 78.2
//   8-row loop 82.5 | fused 512-thr pair 78.0 | __ldcs 79.9 | v1 ~77.4

#define D_DIM 4096
#define THREADS 256

__device__ __forceinline__ void ldg256(const float* __restrict__ p, float v[8]) {
    asm("ld.global.nc.v8.f32 {%0,%1,%2,%3,%4,%5,%6,%7}, [%8];"
        : "=f"(v[0]), "=f"(v[1]), "=f"(v[2]), "=f"(v[3]),
          "=f"(v[4]), "=f"(v[5]), "=f"(v[6]), "=f"(v[7])
        : "l"(p));
}

__global__ __launch_bounds__(THREADS) void cosine_rows_v8_kernel(
    const float* __restrict__ x1,
    const float* __restrict__ x2,
    float* __restrict__ out)
{
    const int row = blockIdx.x;
    const int tid = threadIdx.x;

    const float* r1 = x1 + (size_t)row * D_DIM;
    const float* r2 = x2 + (size_t)row * D_DIM;

    // Per thread: 2 x v8 per input = 16 floats per input (128 B/thread).
    float a0[8], a1[8], b0[8], b1[8];
    ldg256(r1 + (size_t)(tid + 0 * THREADS) * 8, a0);
    ldg256(r1 + (size_t)(tid + 1 * THREADS) * 8, a1);
    ldg256(r2 + (size_t)(tid + 0 * THREADS) * 8, b0);
    ldg256(r2 + (size_t)(tid + 1 * THREADS) * 8, b1);

    float dot = 0.f, sx = 0.f, sy = 0.f;
#pragma unroll
    for (int i = 0; i < 8; ++i) {
        dot = fmaf(a0[i], b0[i], dot);
        sx  = fmaf(a0[i], a0[i], sx);
        sy  = fmaf(b0[i], b0[i], sy);
    }
#pragma unroll
    for (int i = 0; i < 8; ++i) {
        dot = fmaf(a1[i], b1[i], dot);
        sx  = fmaf(a1[i], a1[i], sx);
        sy  = fmaf(b1[i], b1[i], sy);
    }

    // Warp reduce (3 values)
#pragma unroll
    for (int off = 16; off > 0; off >>= 1) {
        dot += __shfl_down_sync(0xFFFFFFFFu, dot, off);
        sx  += __shfl_down_sync(0xFFFFFFFFu, sx,  off);
        sy  += __shfl_down_sync(0xFFFFFFFFu, sy,  off);
    }

    __shared__ float s_dot[8], s_sx[8], s_sy[8];
    const int wid = tid >> 5;
    const int lid = tid & 31;
    if (lid == 0) { s_dot[wid] = dot; s_sx[wid] = sx; s_sy[wid] = sy; }
    __syncthreads();

    if (wid == 0) {
        dot = (lid < 8) ? s_dot[lid] : 0.f;
        sx  = (lid < 8) ? s_sx[lid]  : 0.f;
        sy  = (lid < 8) ? s_sy[lid]  : 0.f;
#pragma unroll
        for (int off = 4; off > 0; off >>= 1) {
            dot += __shfl_down_sync(0xFFFFFFFFu, dot, off);
            sx  += __shfl_down_sync(0xFFFFFFFFu, sx,  off);
            sy  += __shfl_down_sync(0xFFFFFFFFu, sy,  off);
        }
        if (lid == 0) {
            out[row] = 0.5f * dot * rsqrtf(sx * sy);
        }
    }
}

extern "C" void kernel_launch(void* const* d_in, const int* in_sizes, int n_in,
                              void* d_out, int out_size)
{
    const float* x1 = (const float*)d_in[0];
    const float* x2 = (const float*)d_in[1];
    float* out = (float*)d_out;
    const int B = out_size;  // 16384 rows
    cosine_rows_v8_kernel<<<B, THREADS>>>(x1, x2, out);
}